// round 11
// baseline (speedup 1.0000x reference)
#include <cuda_runtime.h>
#include <cuda_bf16.h>
#include <stdint.h>
#include <math.h>

// Problem constants
#define B_   2
#define S_   2048
#define D_   1024
#define H_   16
#define HD_  64
#define M_TOT (B_*S_)     // 4096
#define N_QKV (3*D_)      // 3072

// ---------------------------------------------------------------------------
// Scratch (allocation-free rule: __device__ globals)
// ---------------------------------------------------------------------------
__device__ __nv_bfloat16 g_x_hi [(size_t)M_TOT * D_];
__device__ __nv_bfloat16 g_x_lo [(size_t)M_TOT * D_];
__device__ __nv_bfloat16 g_wq_hi[(size_t)N_QKV * D_];
__device__ __nv_bfloat16 g_wq_lo[(size_t)N_QKV * D_];
__device__ __nv_bfloat16 g_at_hi[(size_t)M_TOT * D_];   // attention out (split)
__device__ __nv_bfloat16 g_at_lo[(size_t)M_TOT * D_];
__device__ __nv_bfloat16 g_wo_hi[(size_t)D_ * D_];
__device__ __nv_bfloat16 g_wo_lo[(size_t)D_ * D_];

// Head-contiguous attention operands (split), written by gemm0 epilogue
__device__ __nv_bfloat16 g_aq_hi [(size_t)B_*H_*S_*HD_];  // [bh][S][64], q/64
__device__ __nv_bfloat16 g_aq_lo [(size_t)B_*H_*S_*HD_];
__device__ __nv_bfloat16 g_ak_hi [(size_t)B_*H_*S_*HD_];  // [bh][S][64]
__device__ __nv_bfloat16 g_ak_lo [(size_t)B_*H_*S_*HD_];
__device__ __nv_bfloat16 g_avt_hi[(size_t)B_*H_*HD_*S_];  // [bh][64][S]  (V^T)
__device__ __nv_bfloat16 g_avt_lo[(size_t)B_*H_*HD_*S_];

// ---------------------------------------------------------------------------
// helpers
// ---------------------------------------------------------------------------
__device__ __forceinline__ uint32_t pack_bf2(float lo, float hi) {
    __nv_bfloat162 t = __floats2bfloat162_rn(lo, hi);   // .x = lo half
    return *(uint32_t*)&t;
}
__device__ __forceinline__ void split1(float v, float& h, float& l) {
    __nv_bfloat16 hb = __float2bfloat16_rn(v);
    h = __bfloat162float(hb);
    l = v - h;
}
__device__ __forceinline__ void mma16816(float* c, const uint32_t* a, const uint32_t* b)
{
    asm volatile(
        "mma.sync.aligned.m16n8k16.row.col.f32.bf16.bf16.f32 "
        "{%0,%1,%2,%3}, {%4,%5,%6,%7}, {%8,%9}, {%0,%1,%2,%3};\n"
        : "+f"(c[0]), "+f"(c[1]), "+f"(c[2]), "+f"(c[3])
        : "r"(a[0]), "r"(a[1]), "r"(a[2]), "r"(a[3]), "r"(b[0]), "r"(b[1]));
}
__device__ __forceinline__ void ldsm_x4(uint32_t* r, uint32_t addr)
{
    asm volatile(
        "ldmatrix.sync.aligned.m8n8.x4.shared.b16 {%0,%1,%2,%3}, [%4];\n"
        : "=r"(r[0]), "=r"(r[1]), "=r"(r[2]), "=r"(r[3]) : "r"(addr));
}
__device__ __forceinline__ void cp16(uint32_t dst, const void* src)
{
    asm volatile("cp.async.cg.shared.global [%0], [%1], 16;\n" :: "r"(dst), "l"(src));
}

// ---------------------------------------------------------------------------
// Elementwise split for GEMM inputs: a -> (hi, lo)
// ---------------------------------------------------------------------------
template<int ID>
__global__ void split_bf16(const float* __restrict__ src, int n4)
{
    __nv_bfloat16* hi = (ID == 0) ? g_x_hi : (ID == 1) ? g_wq_hi : g_wo_hi;
    __nv_bfloat16* lo = (ID == 0) ? g_x_lo : (ID == 1) ? g_wq_lo : g_wo_lo;

    for (int i = blockIdx.x * blockDim.x + threadIdx.x; i < n4;
         i += gridDim.x * blockDim.x) {
        float4 v = ((const float4*)src)[i];
        float h0,l0,h1,l1,h2,l2,h3,l3;
        split1(v.x,h0,l0); split1(v.y,h1,l1); split1(v.z,h2,l2); split1(v.w,h3,l3);
        ((uint32_t*)hi)[2*i + 0] = pack_bf2(h0, h1);
        ((uint32_t*)hi)[2*i + 1] = pack_bf2(h2, h3);
        ((uint32_t*)lo)[2*i + 0] = pack_bf2(l0, l1);
        ((uint32_t*)lo)[2*i + 1] = pack_bf2(l2, l3);
    }
}

// ---------------------------------------------------------------------------
// bf16x3-split tensor-core NT GEMM, 128x256 CTA tile / 64x64 warp tile.
// 8 warps (2x4). BK=32, 3-stage cp.async pipeline.
// Smem-per-output halved vs 128x128/32x64 -> smem port no longer co-saturates
// the crossbar with LDSM + cp.async; tensor pipe becomes the binding pipe.
// MODE 0: epilogue fuses the qkv repack. MODE 1: C = d_out + bias.
// Row layout: 20 uint32 words (16 data + 4 pad), conflict-free for ldmatrix.
// ---------------------------------------------------------------------------
#define GLDW  20
#define AARRB (128 * GLDW * 4)          // A array bytes: 10240
#define BARRB (256 * GLDW * 4)          // B array bytes: 20480
#define GSTGB (2 * AARRB + 2 * BARRB)   // stage bytes:   61440
#define GEMM_SMEM_BYTES (3 * GSTGB)     // 184320

template<int MODE>
__global__ __launch_bounds__(256, 1)
void gemm_bf16x3(const float* __restrict__ bias, float* __restrict__ C_out,
                 int M, int N, int K)
{
    extern __shared__ uint32_t gsm[];

    const __nv_bfloat16 *Ah, *Al, *Bh, *Bl;
    if (MODE == 0) { Ah = g_x_hi;  Al = g_x_lo;  Bh = g_wq_hi; Bl = g_wq_lo; }
    else           { Ah = g_at_hi; Al = g_at_lo; Bh = g_wo_hi; Bl = g_wo_lo; }

    const int tid  = threadIdx.x;
    const int lane = tid & 31;
    const int warp = tid >> 5;
    const int wr = warp >> 2, wc = warp & 3;     // 2x4 warp grid
    const int gid = lane >> 2, tig = lane & 3;

    const int bm = blockIdx.y * 128;
    const int bn = blockIdx.x * 256;

    const uint32_t sb = (uint32_t)__cvta_generic_to_shared(gsm);

    // loader mapping: 4 threads per row, 16B chunks
    const int lrow   = tid >> 2;          // 0..63
    const int lchunk = tid & 3;           // chunk -> bf16 offset lchunk*8

    #define G_LOAD(T, S) do {                                                   \
        int k0_ = (T) * 32;                                                     \
        uint32_t stg0 = sb + (uint32_t)(S) * GSTGB;                             \
        _Pragma("unroll")                                                       \
        for (int i = 0; i < 2; i++) {                                           \
            int row = lrow + i * 64;                                            \
            uint32_t d0 = stg0 + (uint32_t)(row * GLDW + lchunk * 4) * 4;       \
            size_t asrc = (size_t)(bm + row) * K + k0_ + lchunk * 8;            \
            cp16(d0,         Ah + asrc);                                        \
            cp16(d0 + AARRB, Al + asrc);                                        \
        }                                                                       \
        _Pragma("unroll")                                                       \
        for (int i = 0; i < 4; i++) {                                           \
            int row = lrow + i * 64;                                            \
            uint32_t d0 = stg0 + 2*AARRB + (uint32_t)(row * GLDW + lchunk*4)*4; \
            size_t bsrc = (size_t)(bn + row) * K + k0_ + lchunk * 8;            \
            cp16(d0,         Bh + bsrc);                                        \
            cp16(d0 + BARRB, Bl + bsrc);                                        \
        }                                                                       \
        asm volatile("cp.async.commit_group;\n");                               \
    } while (0)

    // ldmatrix byte offsets within an array (add kcb*32 and stage/array base)
    uint32_t a_off[4], b_off[4];
    #pragma unroll
    for (int mi = 0; mi < 4; mi++)
        a_off[mi] = (uint32_t)((wr*64 + mi*16 + (lane & 15)) * GLDW * 4
                               + (lane >> 4) * 16);
    #pragma unroll
    for (int np = 0; np < 4; np++)
        b_off[np] = (uint32_t)((wc*64 + np*16 + ((lane >> 4) & 1)*8 + (lane & 7))
                               * GLDW * 4 + ((lane >> 3) & 1) * 16);

    float acc[4][8][4] = {};

    const int nt = K / 32;
    G_LOAD(0, 0);
    if (nt > 1) G_LOAD(1, 1);
    if (nt > 2) G_LOAD(2, 2);

    for (int t = 0; t < nt; t++) {
        const int stg = t % 3;
        const int rem = nt - t;           // pending groups = min(3, rem)
        if (rem >= 3)      asm volatile("cp.async.wait_group 2;\n");
        else if (rem == 2) asm volatile("cp.async.wait_group 1;\n");
        else               asm volatile("cp.async.wait_group 0;\n");
        __syncthreads();

        const uint32_t sAh = sb + (uint32_t)(stg * GSTGB);
        const uint32_t sAl = sAh + AARRB;
        const uint32_t sBh = sAh + 2 * AARRB;
        const uint32_t sBl = sBh + BARRB;

        #pragma unroll
        for (int kcb = 0; kcb < 2; kcb++) {
            uint32_t ah[4][4], al[4][4];
            #pragma unroll
            for (int mi = 0; mi < 4; mi++) {
                ldsm_x4(ah[mi], sAh + a_off[mi] + kcb*32);
                ldsm_x4(al[mi], sAl + a_off[mi] + kcb*32);
            }
            #pragma unroll
            for (int np = 0; np < 4; np++) {
                uint32_t bhf[4], blf[4];
                ldsm_x4(bhf, sBh + b_off[np] + kcb*32);
                ldsm_x4(blf, sBl + b_off[np] + kcb*32);
                // term-major: same-acc distance = 8 mma
                #pragma unroll
                for (int term = 0; term < 3; term++) {
                    #pragma unroll
                    for (int sub = 0; sub < 2; sub++) {
                        #pragma unroll
                        for (int mi = 0; mi < 4; mi++) {
                            int ni = np * 2 + sub;
                            if      (term == 0) mma16816(acc[mi][ni], ah[mi], bhf + sub*2);
                            else if (term == 1) mma16816(acc[mi][ni], ah[mi], blf + sub*2);
                            else                mma16816(acc[mi][ni], al[mi], bhf + sub*2);
                        }
                    }
                }
            }
        }
        __syncthreads();
        if (t + 3 < nt) G_LOAD(t + 3, stg);
    }
    #undef G_LOAD

    // ---- Epilogue ----
    if (MODE == 1) {
        #pragma unroll
        for (int mi = 0; mi < 4; mi++) {
            int row = bm + wr * 64 + mi * 16 + gid;
            #pragma unroll
            for (int ni = 0; ni < 8; ni++) {
                int col = bn + wc * 64 + ni * 8 + tig * 2;
                float2 bv = *(const float2*)(bias + col);
                float2 v0 = make_float2(acc[mi][ni][0] + bv.x, acc[mi][ni][1] + bv.y);
                float2 v1 = make_float2(acc[mi][ni][2] + bv.x, acc[mi][ni][3] + bv.y);
                *(float2*)(C_out + (size_t)row * N + col)       = v0;
                *(float2*)(C_out + (size_t)(row + 8) * N + col) = v1;
            }
        }
    } else {
        // Fused qkv repack
        #pragma unroll
        for (int mi = 0; mi < 4; mi++) {
            const int row  = bm + wr * 64 + mi * 16 + gid;
            const int bidx = row >> 11;
            const int tokA = row & 2047;
            const int tokB = tokA + 8;
            #pragma unroll
            for (int ni = 0; ni < 8; ni++) {
                int col = bn + wc * 64 + ni * 8 + tig * 2;
                int h   = col / 192;
                int r   = col - h * 192;
                int bh  = bidx * H_ + h;
                float v0 = acc[mi][ni][0], v1 = acc[mi][ni][1];
                float v2 = acc[mi][ni][2], v3 = acc[mi][ni][3];
                float h0,l0,h1,l1,h2,l2,h3,l3;
                if (r < 128) {
                    __nv_bfloat16 *dh, *dl;
                    int d;
                    if (r < 64) {
                        d = r;
                        v0 *= (1.0f/HD_); v1 *= (1.0f/HD_);
                        v2 *= (1.0f/HD_); v3 *= (1.0f/HD_);
                        dh = g_aq_hi; dl = g_aq_lo;
                    } else {
                        d = r - 64;
                        dh = g_ak_hi; dl = g_ak_lo;
                    }
                    split1(v0,h0,l0); split1(v1,h1,l1);
                    split1(v2,h2,l2); split1(v3,h3,l3);
                    size_t i0 = ((size_t)bh * S_ + tokA) * HD_ + d;
                    size_t i1 = ((size_t)bh * S_ + tokB) * HD_ + d;
                    *(uint32_t*)(dh + i0) = pack_bf2(h0, h1);
                    *(uint32_t*)(dl + i0) = pack_bf2(l0, l1);
                    *(uint32_t*)(dh + i1) = pack_bf2(h2, h3);
                    *(uint32_t*)(dl + i1) = pack_bf2(l2, l3);
                } else {
                    int d = r - 128;
                    split1(v0,h0,l0); split1(v1,h1,l1);
                    split1(v2,h2,l2); split1(v3,h3,l3);
                    size_t r0 = ((size_t)bh * HD_ + d)     * S_;
                    size_t r1 = ((size_t)bh * HD_ + d + 1) * S_;
                    g_avt_hi[r0 + tokA] = __float2bfloat16_rn(h0);
                    g_avt_hi[r1 + tokA] = __float2bfloat16_rn(h1);
                    g_avt_hi[r0 + tokB] = __float2bfloat16_rn(h2);
                    g_avt_hi[r1 + tokB] = __float2bfloat16_rn(h3);
                    g_avt_lo[r0 + tokA] = __float2bfloat16_rn(l0);
                    g_avt_lo[r1 + tokA] = __float2bfloat16_rn(l1);
                    g_avt_lo[r0 + tokB] = __float2bfloat16_rn(l2);
                    g_avt_lo[r1 + tokB] = __float2bfloat16_rn(l3);
                }
            }
        }
    }
}

// ---------------------------------------------------------------------------
// Tensor-core causal flash attention (unchanged, passing R10).
// ---------------------------------------------------------------------------
#define ROW_W   36
#define ARR_W   (64 * ROW_W)
#define BUF_W   (4 * ARR_W)
#define ATTN_SMEM_BYTES (2 * BUF_W * 4)

__global__ __launch_bounds__(256)
void attn_mma()
{
    extern __shared__ uint32_t smw[];
    const int tid  = threadIdx.x;
    const int w    = tid >> 5, lane = tid & 31;
    const int gid  = lane >> 2, tig = lane & 3;
    const int bx   = blockIdx.x, bh = blockIdx.y;
    const int b    = bh >> 4;
    const int h    = bh & 15;
    const int rA   = bx * 128 + w * 16 + gid;
    const int rB   = rA + 8;

    const uint32_t* qh_p = (const uint32_t*)(g_aq_hi + ((size_t)bh * S_ + bx*128 + w*16) * HD_);
    const uint32_t* ql_p = (const uint32_t*)(g_aq_lo + ((size_t)bh * S_ + bx*128 + w*16) * HD_);
    uint32_t qh[4][4], ql[4][4];
    #pragma unroll
    for (int kc = 0; kc < 4; kc++) {
        int w0 = 8*kc + tig;
        qh[kc][0] = qh_p[ gid      * 32 + w0    ];
        qh[kc][1] = qh_p[(gid + 8) * 32 + w0    ];
        qh[kc][2] = qh_p[ gid      * 32 + w0 + 4];
        qh[kc][3] = qh_p[(gid + 8) * 32 + w0 + 4];
        ql[kc][0] = ql_p[ gid      * 32 + w0    ];
        ql[kc][1] = ql_p[(gid + 8) * 32 + w0    ];
        ql[kc][2] = ql_p[ gid      * 32 + w0 + 4];
        ql[kc][3] = ql_p[(gid + 8) * 32 + w0 + 4];
    }

    float o[8][4] = {};
    float mA = -INFINITY, mB = -INFINITY, lA = 0.f, lB = 0.f;

    const __nv_bfloat16* kh_p = g_ak_hi  + (size_t)bh * S_ * HD_;
    const __nv_bfloat16* kl_p = g_ak_lo  + (size_t)bh * S_ * HD_;
    const __nv_bfloat16* vh_p = g_avt_hi + (size_t)bh * HD_ * S_;
    const __nv_bfloat16* vl_p = g_avt_lo + (size_t)bh * HD_ * S_;

    const uint32_t sb = (uint32_t)__cvta_generic_to_shared(smw);
    const int lr  = tid >> 3;
    const int seg = tid & 7;

    const uint32_t frag_off = (uint32_t)((lane & 7) * ROW_W * 4 + (lane >> 3) * 16);

    #define LOAD_KV(T, BUF) do {                                                \
        _Pragma("unroll")                                                       \
        for (int i = 0; i < 8; i++) {                                           \
            int arr = i >> 1;                                                   \
            int r   = (i & 1) * 32 + lr;                                        \
            uint32_t dst = sb + ((BUF)*BUF_W + arr*ARR_W + r*ROW_W + seg*4)*4;  \
            const __nv_bfloat16* srcp;                                          \
            if      (arr == 0) srcp = kh_p + (size_t)((T)*64 + r) * HD_ + seg*8;\
            else if (arr == 1) srcp = kl_p + (size_t)((T)*64 + r) * HD_ + seg*8;\
            else if (arr == 2) srcp = vh_p + (size_t)r * S_ + (T)*64 + seg*8;   \
            else               srcp = vl_p + (size_t)r * S_ + (T)*64 + seg*8;   \
            asm volatile("cp.async.cg.shared.global [%0], [%1], 16;\n"          \
                :: "r"(dst), "l"(srcp));                                        \
        }                                                                       \
        asm volatile("cp.async.commit_group;\n");                               \
    } while (0)

    #define MMA_PAIR(ACC0, ACC1, AH, AL, F0H, F0L, F1H, F1L, KP) do {           \
        mma16816(ACC0, AH[2*(KP)],   F0H);     mma16816(ACC1, AH[2*(KP)],   F1H);     \
        mma16816(ACC0, AH[2*(KP)],   F0L);     mma16816(ACC1, AH[2*(KP)],   F1L);     \
        mma16816(ACC0, AL[2*(KP)],   F0H);     mma16816(ACC1, AL[2*(KP)],   F1H);     \
        mma16816(ACC0, AH[2*(KP)+1], F0H + 2); mma16816(ACC1, AH[2*(KP)+1], F1H + 2); \
        mma16816(ACC0, AH[2*(KP)+1], F0L + 2); mma16816(ACC1, AH[2*(KP)+1], F1L + 2); \
        mma16816(ACC0, AL[2*(KP)+1], F0H + 2); mma16816(ACC1, AL[2*(KP)+1], F1H + 2); \
    } while (0)

    const int nt = 2 * (bx + 1);
    LOAD_KV(0, 0);

    for (int t = 0; t < nt; t++) {
        const int buf = t & 1;
        if (t + 1 < nt) {
            LOAD_KV(t + 1, (t + 1) & 1);
            asm volatile("cp.async.wait_group 1;\n");
        } else {
            asm volatile("cp.async.wait_group 0;\n");
        }
        __syncthreads();

        const uint32_t sKH = sb + (uint32_t)(buf * BUF_W) * 4;
        const uint32_t sKL = sKH + ARR_W * 4;
        const uint32_t sVH = sKH + 2 * ARR_W * 4;
        const uint32_t sVL = sKH + 3 * ARR_W * 4;

        float s[8][4];
        #pragma unroll
        for (int ni = 0; ni < 8; ni++) { s[ni][0]=0; s[ni][1]=0; s[ni][2]=0; s[ni][3]=0; }
        #pragma unroll
        for (int nn = 0; nn < 4; nn++) {
            uint32_t off0 = (uint32_t)((2*nn)   * 8 * ROW_W * 4) + frag_off;
            uint32_t off1 = (uint32_t)((2*nn+1) * 8 * ROW_W * 4) + frag_off;
            #pragma unroll
            for (int kp = 0; kp < 2; kp++) {
                uint32_t k0h[4], k0l[4], k1h[4], k1l[4];
                ldsm_x4(k0h, sKH + off0 + kp*64);
                ldsm_x4(k0l, sKL + off0 + kp*64);
                ldsm_x4(k1h, sKH + off1 + kp*64);
                ldsm_x4(k1l, sKL + off1 + kp*64);
                MMA_PAIR(s[2*nn], s[2*nn+1], qh, ql, k0h, k0l, k1h, k1l, kp);
            }
        }

        if (t >= 2 * bx) {
            #pragma unroll
            for (int ni = 0; ni < 8; ni++) {
                int c0 = t * 64 + ni * 8 + 2 * tig;
                if (c0     > rA) s[ni][0] = -1e30f;
                if (c0 + 1 > rA) s[ni][1] = -1e30f;
                if (c0     > rB) s[ni][2] = -1e30f;
                if (c0 + 1 > rB) s[ni][3] = -1e30f;
            }
        }

        float tmA = -INFINITY, tmB = -INFINITY;
        #pragma unroll
        for (int ni = 0; ni < 8; ni++) {
            tmA = fmaxf(tmA, fmaxf(s[ni][0], s[ni][1]));
            tmB = fmaxf(tmB, fmaxf(s[ni][2], s[ni][3]));
        }
        tmA = fmaxf(tmA, __shfl_xor_sync(0xffffffffu, tmA, 1));
        tmA = fmaxf(tmA, __shfl_xor_sync(0xffffffffu, tmA, 2));
        tmB = fmaxf(tmB, __shfl_xor_sync(0xffffffffu, tmB, 1));
        tmB = fmaxf(tmB, __shfl_xor_sync(0xffffffffu, tmB, 2));

        float mnA = fmaxf(mA, tmA), mnB = fmaxf(mB, tmB);
        float sfA = __expf(mA - mnA), sfB = __expf(mB - mnB);
        float lsA = 0.f, lsB = 0.f;

        uint32_t ph[4][4], pl[4][4];
        #pragma unroll
        for (int ni = 0; ni < 8; ni++) {
            float e0 = __expf(s[ni][0] - mnA);
            float e1 = __expf(s[ni][1] - mnA);
            float e2 = __expf(s[ni][2] - mnB);
            float e3 = __expf(s[ni][3] - mnB);
            lsA += e0 + e1;  lsB += e2 + e3;
            float h0,l0,h1,l1,h2,l2,h3,l3;
            split1(e0,h0,l0); split1(e1,h1,l1); split1(e2,h2,l2); split1(e3,h3,l3);
            int kc = ni >> 1, off = (ni & 1) * 2;
            ph[kc][off]     = pack_bf2(h0, h1);
            ph[kc][off + 1] = pack_bf2(h2, h3);
            pl[kc][off]     = pack_bf2(l0, l1);
            pl[kc][off + 1] = pack_bf2(l2, l3);
        }
        lsA += __shfl_xor_sync(0xffffffffu, lsA, 1);
        lsA += __shfl_xor_sync(0xffffffffu, lsA, 2);
        lsB += __shfl_xor_sync(0xffffffffu, lsB, 1);
        lsB += __shfl_xor_sync(0xffffffffu, lsB, 2);

        mA = mnA; mB = mnB;
        lA = lA * sfA + lsA;
        lB = lB * sfB + lsB;

        #pragma unroll
        for (int nd = 0; nd < 8; nd++) {
            o[nd][0] *= sfA; o[nd][1] *= sfA;
            o[nd][2] *= sfB; o[nd][3] *= sfB;
        }

        #pragma unroll
        for (int nn = 0; nn < 4; nn++) {
            uint32_t off0 = (uint32_t)((2*nn)   * 8 * ROW_W * 4) + frag_off;
            uint32_t off1 = (uint32_t)((2*nn+1) * 8 * ROW_W * 4) + frag_off;
            #pragma unroll
            for (int kp = 0; kp < 2; kp++) {
                uint32_t v0h[4], v0l[4], v1h[4], v1l[4];
                ldsm_x4(v0h, sVH + off0 + kp*64);
                ldsm_x4(v0l, sVL + off0 + kp*64);
                ldsm_x4(v1h, sVH + off1 + kp*64);
                ldsm_x4(v1l, sVL + off1 + kp*64);
                MMA_PAIR(o[2*nn], o[2*nn+1], ph, pl, v0h, v0l, v1h, v1l, kp);
            }
        }
        __syncthreads();
    }
    #undef LOAD_KV
    #undef MMA_PAIR

    const float iA = 1.0f / lA, iB = 1.0f / lB;
    const size_t gRowA = (size_t)(b * S_ + rA);
    const size_t gRowB = (size_t)(b * S_ + rB);
    #pragma unroll
    for (int nd = 0; nd < 8; nd++) {
        float v0 = o[nd][0] * iA, v1 = o[nd][1] * iA;
        float v2 = o[nd][2] * iB, v3 = o[nd][3] * iB;
        float h0,l0,h1,l1,h2,l2,h3,l3;
        split1(v0,h0,l0); split1(v1,h1,l1); split1(v2,h2,l2); split1(v3,h3,l3);
        size_t i0 = gRowA * D_ + h * HD_ + nd * 8 + 2 * tig;
        size_t i1 = gRowB * D_ + h * HD_ + nd * 8 + 2 * tig;
        *(uint32_t*)(g_at_hi + i0) = pack_bf2(h0, h1);
        *(uint32_t*)(g_at_lo + i0) = pack_bf2(l0, l1);
        *(uint32_t*)(g_at_hi + i1) = pack_bf2(h2, h3);
        *(uint32_t*)(g_at_lo + i1) = pack_bf2(l2, l3);
    }
}

// ---------------------------------------------------------------------------
extern "C" void kernel_launch(void* const* d_in, const int* in_sizes, int n_in,
                              void* d_out, int out_size)
{
    const float* x = nullptr, *w_qkv = nullptr, *w_out = nullptr, *b_out = nullptr;
    for (int i = 0; i < n_in; i++) {
        long long n = in_sizes[i];
        if      (n == (long long)B_ * S_ * D_)      x     = (const float*)d_in[i];
        else if (n == (long long)N_QKV * D_)        w_qkv = (const float*)d_in[i];
        else if (n == (long long)D_ * D_)           w_out = (const float*)d_in[i];
        else if (n == (long long)D_)                b_out = (const float*)d_in[i];
        // mask ignored: causality is static
    }
    float* out = (float*)d_out;

    cudaFuncSetAttribute(attn_mma, cudaFuncAttributeMaxDynamicSharedMemorySize,
                         ATTN_SMEM_BYTES);
    cudaFuncSetAttribute(gemm_bf16x3<0>, cudaFuncAttributeMaxDynamicSharedMemorySize,
                         GEMM_SMEM_BYTES);
    cudaFuncSetAttribute(gemm_bf16x3<1>, cudaFuncAttributeMaxDynamicSharedMemorySize,
                         GEMM_SMEM_BYTES);

    // 0) Split GEMM inputs into bf16 hi/lo
    split_bf16<0><<<4096, 256>>>(x,     (M_TOT * D_) / 4);
    split_bf16<1><<<3072, 256>>>(w_qkv, (N_QKV * D_) / 4);
    split_bf16<2><<<1024, 256>>>(w_out, (D_ * D_) / 4);

    // 1) QKV projection + fused repack (128x256 tiles)
    gemm_bf16x3<0><<<dim3(N_QKV / 256, M_TOT / 128), 256, GEMM_SMEM_BYTES>>>(
        nullptr, nullptr, M_TOT, N_QKV, D_);

    // 2) Tensor-core causal flash attention -> g_at_hi/lo
    attn_mma<<<dim3(S_ / 128, B_ * H_), 256, ATTN_SMEM_BYTES>>>();

    // 3) Output projection: out = attn @ w_out^T + b_out
    gemm_bf16x3<1><<<dim3(D_ / 256, M_TOT / 128), 256, GEMM_SMEM_BYTES>>>(
        b_out, out, M_TOT, D_, D_);
}

// round 12
// speedup vs baseline: 1.1401x; 1.1401x over previous
#include <cuda_runtime.h>
#include <cuda_bf16.h>
#include <stdint.h>
#include <math.h>

// Problem constants
#define B_   2
#define S_   2048
#define D_   1024
#define H_   16
#define HD_  64
#define M_TOT (B_*S_)     // 4096
#define N_QKV (3*D_)      // 3072

// ---------------------------------------------------------------------------
// Scratch (allocation-free rule: __device__ globals)
// ---------------------------------------------------------------------------
__device__ __nv_bfloat16 g_x_hi [(size_t)M_TOT * D_];
__device__ __nv_bfloat16 g_x_lo [(size_t)M_TOT * D_];
__device__ __nv_bfloat16 g_wq_hi[(size_t)N_QKV * D_];
__device__ __nv_bfloat16 g_wq_lo[(size_t)N_QKV * D_];
__device__ __nv_bfloat16 g_at_hi[(size_t)M_TOT * D_];   // attention out (split)
__device__ __nv_bfloat16 g_at_lo[(size_t)M_TOT * D_];
__device__ __nv_bfloat16 g_wo_hi[(size_t)D_ * D_];
__device__ __nv_bfloat16 g_wo_lo[(size_t)D_ * D_];

// Head-contiguous attention operands (split), written by gemm0 epilogue
__device__ __nv_bfloat16 g_aq_hi [(size_t)B_*H_*S_*HD_];  // [bh][S][64], q/64
__device__ __nv_bfloat16 g_aq_lo [(size_t)B_*H_*S_*HD_];
__device__ __nv_bfloat16 g_ak_hi [(size_t)B_*H_*S_*HD_];  // [bh][S][64]
__device__ __nv_bfloat16 g_ak_lo [(size_t)B_*H_*S_*HD_];
__device__ __nv_bfloat16 g_avt_hi[(size_t)B_*H_*HD_*S_];  // [bh][64][S]  (V^T)
__device__ __nv_bfloat16 g_avt_lo[(size_t)B_*H_*HD_*S_];

// ---------------------------------------------------------------------------
// helpers
// ---------------------------------------------------------------------------
__device__ __forceinline__ uint32_t pack_bf2(float lo, float hi) {
    __nv_bfloat162 t = __floats2bfloat162_rn(lo, hi);   // .x = lo half
    return *(uint32_t*)&t;
}
__device__ __forceinline__ void split1(float v, float& h, float& l) {
    __nv_bfloat16 hb = __float2bfloat16_rn(v);
    h = __bfloat162float(hb);
    l = v - h;
}
__device__ __forceinline__ void mma16816(float* c, const uint32_t* a, const uint32_t* b)
{
    asm volatile(
        "mma.sync.aligned.m16n8k16.row.col.f32.bf16.bf16.f32 "
        "{%0,%1,%2,%3}, {%4,%5,%6,%7}, {%8,%9}, {%0,%1,%2,%3};\n"
        : "+f"(c[0]), "+f"(c[1]), "+f"(c[2]), "+f"(c[3])
        : "r"(a[0]), "r"(a[1]), "r"(a[2]), "r"(a[3]), "r"(b[0]), "r"(b[1]));
}
__device__ __forceinline__ void ldsm_x4(uint32_t* r, uint32_t addr)
{
    asm volatile(
        "ldmatrix.sync.aligned.m8n8.x4.shared.b16 {%0,%1,%2,%3}, [%4];\n"
        : "=r"(r[0]), "=r"(r[1]), "=r"(r[2]), "=r"(r[3]) : "r"(addr));
}

// ---------------------------------------------------------------------------
// Elementwise split for GEMM inputs: a -> (hi, lo)
// ---------------------------------------------------------------------------
template<int ID>
__global__ void split_bf16(const float* __restrict__ src, int n4)
{
    __nv_bfloat16* hi = (ID == 0) ? g_x_hi : (ID == 1) ? g_wq_hi : g_wo_hi;
    __nv_bfloat16* lo = (ID == 0) ? g_x_lo : (ID == 1) ? g_wq_lo : g_wo_lo;

    for (int i = blockIdx.x * blockDim.x + threadIdx.x; i < n4;
         i += gridDim.x * blockDim.x) {
        float4 v = ((const float4*)src)[i];
        float h0,l0,h1,l1,h2,l2,h3,l3;
        split1(v.x,h0,l0); split1(v.y,h1,l1); split1(v.z,h2,l2); split1(v.w,h3,l3);
        ((uint32_t*)hi)[2*i + 0] = pack_bf2(h0, h1);
        ((uint32_t*)hi)[2*i + 1] = pack_bf2(h2, h3);
        ((uint32_t*)lo)[2*i + 0] = pack_bf2(l0, l1);
        ((uint32_t*)lo)[2*i + 1] = pack_bf2(l2, l3);
    }
}

// ---------------------------------------------------------------------------
// bf16x3-split tensor-core NT GEMM (R10 config: 128x128 tile, 2 CTA/SM).
// MODE 0: epilogue fuses the qkv repack. MODE 1: C = d_out + bias.
// ---------------------------------------------------------------------------
#define GLDW 20
#define GARR (128 * GLDW)
#define GSTG (4 * GARR)
#define GEMM_SMEM_BYTES (2 * GSTG * 4)   // 81920

template<int MODE>
__global__ __launch_bounds__(256, 2)
void gemm_bf16x3(const float* __restrict__ bias, float* __restrict__ C_out,
                 int M, int N, int K)
{
    extern __shared__ uint32_t gsm[];

    const __nv_bfloat16 *Ah, *Al, *Bh, *Bl;
    if (MODE == 0) { Ah = g_x_hi;  Al = g_x_lo;  Bh = g_wq_hi; Bl = g_wq_lo; }
    else           { Ah = g_at_hi; Al = g_at_lo; Bh = g_wo_hi; Bl = g_wo_lo; }

    const int tid  = threadIdx.x;
    const int lane = tid & 31;
    const int warp = tid >> 5;
    const int wr = warp >> 1, wc = warp & 1;
    const int gid = lane >> 2, tig = lane & 3;

    const int bm = blockIdx.y * 128;
    const int bn = blockIdx.x * 128;

    const int lrow   = tid >> 2;
    const int lchunk = tid & 3;

    const uint32_t sb = (uint32_t)__cvta_generic_to_shared(gsm);

    #define G_LOAD(T, S) do {                                                   \
        int k0_ = (T) * 32;                                                     \
        _Pragma("unroll")                                                       \
        for (int hh = 0; hh < 2; hh++) {                                        \
            int row = lrow + hh * 64;                                           \
            uint32_t d0 = sb + (uint32_t)((S)*GSTG + row*GLDW + lchunk*4) * 4;  \
            size_t asrc = (size_t)(bm + row) * K + k0_ + lchunk*8;              \
            size_t bsrc = (size_t)(bn + row) * K + k0_ + lchunk*8;              \
            asm volatile("cp.async.cg.shared.global [%0], [%1], 16;\n"          \
                :: "r"(d0),              "l"(Ah + asrc));                       \
            asm volatile("cp.async.cg.shared.global [%0], [%1], 16;\n"          \
                :: "r"(d0 + GARR*4),     "l"(Al + asrc));                       \
            asm volatile("cp.async.cg.shared.global [%0], [%1], 16;\n"          \
                :: "r"(d0 + 2*GARR*4),   "l"(Bh + bsrc));                       \
            asm volatile("cp.async.cg.shared.global [%0], [%1], 16;\n"          \
                :: "r"(d0 + 3*GARR*4),   "l"(Bl + bsrc));                       \
        }                                                                       \
        asm volatile("cp.async.commit_group;\n");                               \
    } while (0)

    uint32_t a_off[2], b_off[4];
    #pragma unroll
    for (int mi = 0; mi < 2; mi++)
        a_off[mi] = (uint32_t)((wr*32 + mi*16 + (lane & 15)) * GLDW * 4
                               + (lane >> 4) * 16);
    #pragma unroll
    for (int np = 0; np < 4; np++)
        b_off[np] = (uint32_t)((wc*64 + np*16 + ((lane >> 4) & 1)*8 + (lane & 7))
                               * GLDW * 4 + ((lane >> 3) & 1) * 16);

    float acc[2][8][4] = {};

    const int nt = K / 32;
    G_LOAD(0, 0);

    for (int t = 0; t < nt; t++) {
        const int stg = t & 1;
        if (t + 1 < nt) {
            G_LOAD(t + 1, (t + 1) & 1);
            asm volatile("cp.async.wait_group 1;\n");
        } else {
            asm volatile("cp.async.wait_group 0;\n");
        }
        __syncthreads();

        const uint32_t sAh = sb + (uint32_t)(stg * GSTG) * 4;
        const uint32_t sAl = sAh + GARR * 4;
        const uint32_t sBh = sAh + 2 * GARR * 4;
        const uint32_t sBl = sAh + 3 * GARR * 4;

        #pragma unroll
        for (int kcb = 0; kcb < 2; kcb++) {
            uint32_t ah[2][4], al[2][4];
            ldsm_x4(ah[0], sAh + a_off[0] + kcb*32);
            ldsm_x4(ah[1], sAh + a_off[1] + kcb*32);
            ldsm_x4(al[0], sAl + a_off[0] + kcb*32);
            ldsm_x4(al[1], sAl + a_off[1] + kcb*32);
            #pragma unroll
            for (int np = 0; np < 4; np++) {
                uint32_t bhf[4], blf[4];
                ldsm_x4(bhf, sBh + b_off[np] + kcb*32);
                ldsm_x4(blf, sBl + b_off[np] + kcb*32);
                #pragma unroll
                for (int term = 0; term < 3; term++) {
                    #pragma unroll
                    for (int sub = 0; sub < 2; sub++) {
                        #pragma unroll
                        for (int mi = 0; mi < 2; mi++) {
                            int ni = np * 2 + sub;
                            if      (term == 0) mma16816(acc[mi][ni], ah[mi], bhf + sub*2);
                            else if (term == 1) mma16816(acc[mi][ni], ah[mi], blf + sub*2);
                            else                mma16816(acc[mi][ni], al[mi], bhf + sub*2);
                        }
                    }
                }
            }
        }
        __syncthreads();
    }
    #undef G_LOAD

    // ---- Epilogue ----
    if (MODE == 1) {
        #pragma unroll
        for (int mi = 0; mi < 2; mi++) {
            int row = bm + wr * 32 + mi * 16 + gid;
            #pragma unroll
            for (int ni = 0; ni < 8; ni++) {
                int col = bn + wc * 64 + ni * 8 + tig * 2;
                float2 bv = *(const float2*)(bias + col);
                float2 v0 = make_float2(acc[mi][ni][0] + bv.x, acc[mi][ni][1] + bv.y);
                float2 v1 = make_float2(acc[mi][ni][2] + bv.x, acc[mi][ni][3] + bv.y);
                *(float2*)(C_out + (size_t)row * N + col)       = v0;
                *(float2*)(C_out + (size_t)(row + 8) * N + col) = v1;
            }
        }
    } else {
        // Fused qkv repack
        #pragma unroll
        for (int mi = 0; mi < 2; mi++) {
            const int row  = bm + wr * 32 + mi * 16 + gid;
            const int bidx = row >> 11;
            const int tokA = row & 2047;
            const int tokB = tokA + 8;
            #pragma unroll
            for (int ni = 0; ni < 8; ni++) {
                int col = bn + wc * 64 + ni * 8 + tig * 2;
                int h   = col / 192;
                int r   = col - h * 192;
                int bh  = bidx * H_ + h;
                float v0 = acc[mi][ni][0], v1 = acc[mi][ni][1];
                float v2 = acc[mi][ni][2], v3 = acc[mi][ni][3];
                float h0,l0,h1,l1,h2,l2,h3,l3;
                if (r < 128) {
                    __nv_bfloat16 *dh, *dl;
                    int d;
                    if (r < 64) {
                        d = r;
                        v0 *= (1.0f/HD_); v1 *= (1.0f/HD_);
                        v2 *= (1.0f/HD_); v3 *= (1.0f/HD_);
                        dh = g_aq_hi; dl = g_aq_lo;
                    } else {
                        d = r - 64;
                        dh = g_ak_hi; dl = g_ak_lo;
                    }
                    split1(v0,h0,l0); split1(v1,h1,l1);
                    split1(v2,h2,l2); split1(v3,h3,l3);
                    size_t i0 = ((size_t)bh * S_ + tokA) * HD_ + d;
                    size_t i1 = ((size_t)bh * S_ + tokB) * HD_ + d;
                    *(uint32_t*)(dh + i0) = pack_bf2(h0, h1);
                    *(uint32_t*)(dl + i0) = pack_bf2(l0, l1);
                    *(uint32_t*)(dh + i1) = pack_bf2(h2, h3);
                    *(uint32_t*)(dl + i1) = pack_bf2(l2, l3);
                } else {
                    int d = r - 128;
                    split1(v0,h0,l0); split1(v1,h1,l1);
                    split1(v2,h2,l2); split1(v3,h3,l3);
                    size_t r0 = ((size_t)bh * HD_ + d)     * S_;
                    size_t r1 = ((size_t)bh * HD_ + d + 1) * S_;
                    g_avt_hi[r0 + tokA] = __float2bfloat16_rn(h0);
                    g_avt_hi[r1 + tokA] = __float2bfloat16_rn(h1);
                    g_avt_hi[r0 + tokB] = __float2bfloat16_rn(h2);
                    g_avt_hi[r1 + tokB] = __float2bfloat16_rn(h3);
                    g_avt_lo[r0 + tokA] = __float2bfloat16_rn(l0);
                    g_avt_lo[r1 + tokA] = __float2bfloat16_rn(l1);
                    g_avt_lo[r0 + tokB] = __float2bfloat16_rn(l2);
                    g_avt_lo[r1 + tokB] = __float2bfloat16_rn(l3);
                }
            }
        }
    }
}

// ---------------------------------------------------------------------------
// Tensor-core causal flash attention.
// LPT scheduling: grid is (bh=32, qt=16) with bx = 15 - blockIdx.y so the
// heaviest (diagonal-farthest) blocks launch first; wave>=2 work-stealing
// then packs the light blocks into the tail.
// ---------------------------------------------------------------------------
#define ROW_W   36
#define ARR_W   (64 * ROW_W)
#define BUF_W   (4 * ARR_W)
#define ATTN_SMEM_BYTES (2 * BUF_W * 4)

__global__ __launch_bounds__(256)
void attn_mma()
{
    extern __shared__ uint32_t smw[];
    const int tid  = threadIdx.x;
    const int w    = tid >> 5, lane = tid & 31;
    const int gid  = lane >> 2, tig = lane & 3;
    const int bx   = (int)(gridDim.y - 1 - blockIdx.y);   // LPT: heavy first
    const int bh   = blockIdx.x;
    const int b    = bh >> 4;
    const int h    = bh & 15;
    const int rA   = bx * 128 + w * 16 + gid;
    const int rB   = rA + 8;

    const uint32_t* qh_p = (const uint32_t*)(g_aq_hi + ((size_t)bh * S_ + bx*128 + w*16) * HD_);
    const uint32_t* ql_p = (const uint32_t*)(g_aq_lo + ((size_t)bh * S_ + bx*128 + w*16) * HD_);
    uint32_t qh[4][4], ql[4][4];
    #pragma unroll
    for (int kc = 0; kc < 4; kc++) {
        int w0 = 8*kc + tig;
        qh[kc][0] = qh_p[ gid      * 32 + w0    ];
        qh[kc][1] = qh_p[(gid + 8) * 32 + w0    ];
        qh[kc][2] = qh_p[ gid      * 32 + w0 + 4];
        qh[kc][3] = qh_p[(gid + 8) * 32 + w0 + 4];
        ql[kc][0] = ql_p[ gid      * 32 + w0    ];
        ql[kc][1] = ql_p[(gid + 8) * 32 + w0    ];
        ql[kc][2] = ql_p[ gid      * 32 + w0 + 4];
        ql[kc][3] = ql_p[(gid + 8) * 32 + w0 + 4];
    }

    float o[8][4] = {};
    float mA = -INFINITY, mB = -INFINITY, lA = 0.f, lB = 0.f;

    const __nv_bfloat16* kh_p = g_ak_hi  + (size_t)bh * S_ * HD_;
    const __nv_bfloat16* kl_p = g_ak_lo  + (size_t)bh * S_ * HD_;
    const __nv_bfloat16* vh_p = g_avt_hi + (size_t)bh * HD_ * S_;
    const __nv_bfloat16* vl_p = g_avt_lo + (size_t)bh * HD_ * S_;

    const uint32_t sb = (uint32_t)__cvta_generic_to_shared(smw);
    const int lr  = tid >> 3;
    const int seg = tid & 7;

    const uint32_t frag_off = (uint32_t)((lane & 7) * ROW_W * 4 + (lane >> 3) * 16);

    #define LOAD_KV(T, BUF) do {                                                \
        _Pragma("unroll")                                                       \
        for (int i = 0; i < 8; i++) {                                           \
            int arr = i >> 1;                                                   \
            int r   = (i & 1) * 32 + lr;                                        \
            uint32_t dst = sb + ((BUF)*BUF_W + arr*ARR_W + r*ROW_W + seg*4)*4;  \
            const __nv_bfloat16* srcp;                                          \
            if      (arr == 0) srcp = kh_p + (size_t)((T)*64 + r) * HD_ + seg*8;\
            else if (arr == 1) srcp = kl_p + (size_t)((T)*64 + r) * HD_ + seg*8;\
            else if (arr == 2) srcp = vh_p + (size_t)r * S_ + (T)*64 + seg*8;   \
            else               srcp = vl_p + (size_t)r * S_ + (T)*64 + seg*8;   \
            asm volatile("cp.async.cg.shared.global [%0], [%1], 16;\n"          \
                :: "r"(dst), "l"(srcp));                                        \
        }                                                                       \
        asm volatile("cp.async.commit_group;\n");                               \
    } while (0)

    #define MMA_PAIR(ACC0, ACC1, AH, AL, F0H, F0L, F1H, F1L, KP) do {           \
        mma16816(ACC0, AH[2*(KP)],   F0H);     mma16816(ACC1, AH[2*(KP)],   F1H);     \
        mma16816(ACC0, AH[2*(KP)],   F0L);     mma16816(ACC1, AH[2*(KP)],   F1L);     \
        mma16816(ACC0, AL[2*(KP)],   F0H);     mma16816(ACC1, AL[2*(KP)],   F1H);     \
        mma16816(ACC0, AH[2*(KP)+1], F0H + 2); mma16816(ACC1, AH[2*(KP)+1], F1H + 2); \
        mma16816(ACC0, AH[2*(KP)+1], F0L + 2); mma16816(ACC1, AH[2*(KP)+1], F1L + 2); \
        mma16816(ACC0, AL[2*(KP)+1], F0H + 2); mma16816(ACC1, AL[2*(KP)+1], F1H + 2); \
    } while (0)

    const int nt = 2 * (bx + 1);
    LOAD_KV(0, 0);

    for (int t = 0; t < nt; t++) {
        const int buf = t & 1;
        if (t + 1 < nt) {
            LOAD_KV(t + 1, (t + 1) & 1);
            asm volatile("cp.async.wait_group 1;\n");
        } else {
            asm volatile("cp.async.wait_group 0;\n");
        }
        __syncthreads();

        const uint32_t sKH = sb + (uint32_t)(buf * BUF_W) * 4;
        const uint32_t sKL = sKH + ARR_W * 4;
        const uint32_t sVH = sKH + 2 * ARR_W * 4;
        const uint32_t sVL = sKH + 3 * ARR_W * 4;

        float s[8][4];
        #pragma unroll
        for (int ni = 0; ni < 8; ni++) { s[ni][0]=0; s[ni][1]=0; s[ni][2]=0; s[ni][3]=0; }
        #pragma unroll
        for (int nn = 0; nn < 4; nn++) {
            uint32_t off0 = (uint32_t)((2*nn)   * 8 * ROW_W * 4) + frag_off;
            uint32_t off1 = (uint32_t)((2*nn+1) * 8 * ROW_W * 4) + frag_off;
            #pragma unroll
            for (int kp = 0; kp < 2; kp++) {
                uint32_t k0h[4], k0l[4], k1h[4], k1l[4];
                ldsm_x4(k0h, sKH + off0 + kp*64);
                ldsm_x4(k0l, sKL + off0 + kp*64);
                ldsm_x4(k1h, sKH + off1 + kp*64);
                ldsm_x4(k1l, sKL + off1 + kp*64);
                MMA_PAIR(s[2*nn], s[2*nn+1], qh, ql, k0h, k0l, k1h, k1l, kp);
            }
        }

        if (t >= 2 * bx) {
            #pragma unroll
            for (int ni = 0; ni < 8; ni++) {
                int c0 = t * 64 + ni * 8 + 2 * tig;
                if (c0     > rA) s[ni][0] = -1e30f;
                if (c0 + 1 > rA) s[ni][1] = -1e30f;
                if (c0     > rB) s[ni][2] = -1e30f;
                if (c0 + 1 > rB) s[ni][3] = -1e30f;
            }
        }

        float tmA = -INFINITY, tmB = -INFINITY;
        #pragma unroll
        for (int ni = 0; ni < 8; ni++) {
            tmA = fmaxf(tmA, fmaxf(s[ni][0], s[ni][1]));
            tmB = fmaxf(tmB, fmaxf(s[ni][2], s[ni][3]));
        }
        tmA = fmaxf(tmA, __shfl_xor_sync(0xffffffffu, tmA, 1));
        tmA = fmaxf(tmA, __shfl_xor_sync(0xffffffffu, tmA, 2));
        tmB = fmaxf(tmB, __shfl_xor_sync(0xffffffffu, tmB, 1));
        tmB = fmaxf(tmB, __shfl_xor_sync(0xffffffffu, tmB, 2));

        float mnA = fmaxf(mA, tmA), mnB = fmaxf(mB, tmB);
        float sfA = __expf(mA - mnA), sfB = __expf(mB - mnB);
        float lsA = 0.f, lsB = 0.f;

        uint32_t ph[4][4], pl[4][4];
        #pragma unroll
        for (int ni = 0; ni < 8; ni++) {
            float e0 = __expf(s[ni][0] - mnA);
            float e1 = __expf(s[ni][1] - mnA);
            float e2 = __expf(s[ni][2] - mnB);
            float e3 = __expf(s[ni][3] - mnB);
            lsA += e0 + e1;  lsB += e2 + e3;
            float h0,l0,h1,l1,h2,l2,h3,l3;
            split1(e0,h0,l0); split1(e1,h1,l1); split1(e2,h2,l2); split1(e3,h3,l3);
            int kc = ni >> 1, off = (ni & 1) * 2;
            ph[kc][off]     = pack_bf2(h0, h1);
            ph[kc][off + 1] = pack_bf2(h2, h3);
            pl[kc][off]     = pack_bf2(l0, l1);
            pl[kc][off + 1] = pack_bf2(l2, l3);
        }
        lsA += __shfl_xor_sync(0xffffffffu, lsA, 1);
        lsA += __shfl_xor_sync(0xffffffffu, lsA, 2);
        lsB += __shfl_xor_sync(0xffffffffu, lsB, 1);
        lsB += __shfl_xor_sync(0xffffffffu, lsB, 2);

        mA = mnA; mB = mnB;
        lA = lA * sfA + lsA;
        lB = lB * sfB + lsB;

        #pragma unroll
        for (int nd = 0; nd < 8; nd++) {
            o[nd][0] *= sfA; o[nd][1] *= sfA;
            o[nd][2] *= sfB; o[nd][3] *= sfB;
        }

        #pragma unroll
        for (int nn = 0; nn < 4; nn++) {
            uint32_t off0 = (uint32_t)((2*nn)   * 8 * ROW_W * 4) + frag_off;
            uint32_t off1 = (uint32_t)((2*nn+1) * 8 * ROW_W * 4) + frag_off;
            #pragma unroll
            for (int kp = 0; kp < 2; kp++) {
                uint32_t v0h[4], v0l[4], v1h[4], v1l[4];
                ldsm_x4(v0h, sVH + off0 + kp*64);
                ldsm_x4(v0l, sVL + off0 + kp*64);
                ldsm_x4(v1h, sVH + off1 + kp*64);
                ldsm_x4(v1l, sVL + off1 + kp*64);
                MMA_PAIR(o[2*nn], o[2*nn+1], ph, pl, v0h, v0l, v1h, v1l, kp);
            }
        }
        __syncthreads();
    }
    #undef LOAD_KV
    #undef MMA_PAIR

    const float iA = 1.0f / lA, iB = 1.0f / lB;
    const size_t gRowA = (size_t)(b * S_ + rA);
    const size_t gRowB = (size_t)(b * S_ + rB);
    #pragma unroll
    for (int nd = 0; nd < 8; nd++) {
        float v0 = o[nd][0] * iA, v1 = o[nd][1] * iA;
        float v2 = o[nd][2] * iB, v3 = o[nd][3] * iB;
        float h0,l0,h1,l1,h2,l2,h3,l3;
        split1(v0,h0,l0); split1(v1,h1,l1); split1(v2,h2,l2); split1(v3,h3,l3);
        size_t i0 = gRowA * D_ + h * HD_ + nd * 8 + 2 * tig;
        size_t i1 = gRowB * D_ + h * HD_ + nd * 8 + 2 * tig;
        *(uint32_t*)(g_at_hi + i0) = pack_bf2(h0, h1);
        *(uint32_t*)(g_at_lo + i0) = pack_bf2(l0, l1);
        *(uint32_t*)(g_at_hi + i1) = pack_bf2(h2, h3);
        *(uint32_t*)(g_at_lo + i1) = pack_bf2(l2, l3);
    }
}

// ---------------------------------------------------------------------------
extern "C" void kernel_launch(void* const* d_in, const int* in_sizes, int n_in,
                              void* d_out, int out_size)
{
    const float* x = nullptr, *w_qkv = nullptr, *w_out = nullptr, *b_out = nullptr;
    for (int i = 0; i < n_in; i++) {
        long long n = in_sizes[i];
        if      (n == (long long)B_ * S_ * D_)      x     = (const float*)d_in[i];
        else if (n == (long long)N_QKV * D_)        w_qkv = (const float*)d_in[i];
        else if (n == (long long)D_ * D_)           w_out = (const float*)d_in[i];
        else if (n == (long long)D_)                b_out = (const float*)d_in[i];
        // mask ignored: causality is static
    }
    float* out = (float*)d_out;

    cudaFuncSetAttribute(attn_mma, cudaFuncAttributeMaxDynamicSharedMemorySize,
                         ATTN_SMEM_BYTES);
    cudaFuncSetAttribute(gemm_bf16x3<0>, cudaFuncAttributeMaxDynamicSharedMemorySize,
                         GEMM_SMEM_BYTES);
    cudaFuncSetAttribute(gemm_bf16x3<1>, cudaFuncAttributeMaxDynamicSharedMemorySize,
                         GEMM_SMEM_BYTES);

    // 0) Split GEMM inputs into bf16 hi/lo
    split_bf16<0><<<4096, 256>>>(x,     (M_TOT * D_) / 4);
    split_bf16<1><<<3072, 256>>>(w_qkv, (N_QKV * D_) / 4);
    split_bf16<2><<<1024, 256>>>(w_out, (D_ * D_) / 4);

    // 1) QKV projection + fused repack
    gemm_bf16x3<0><<<dim3(N_QKV / 128, M_TOT / 128), 256, GEMM_SMEM_BYTES>>>(
        nullptr, nullptr, M_TOT, N_QKV, D_);

    // 2) Tensor-core causal flash attention (LPT block order) -> g_at_hi/lo
    attn_mma<<<dim3(B_ * H_, S_ / 128), 256, ATTN_SMEM_BYTES>>>();

    // 3) Output projection: out = attn @ w_out^T + b_out
    gemm_bf16x3<1><<<dim3(D_ / 128, M_TOT / 128), 256, GEMM_SMEM_BYTES>>>(
        b_out, out, M_TOT, D_, D_);
}